// round 15
// baseline (speedup 1.0000x reference)
#include <cuda_runtime.h>
#include <cuda_bf16.h>
#include <cuda_fp16.h>
#include <math.h>
#include <stdint.h>

#define BATCH 2
#define L_SEQ 4096
#define D_MODEL 1024
#define DIP 4384          // D_IN_PROJ
#define DSSM 2048
#define CONVD 2304        // CONV_DIM
#define NH 32
#define HD 64
#define DS 128
#define NC64 64           // chunks of 64 per batch
#define TCH 64
#define HPB 8             // heads per block
#define MROWS (BATCH * L_SEQ)   // 8192

// ---------------- scratch (device globals; no allocation) ----------------
__device__ __half g_zxh[(size_t)MROWS * DIP];
__device__ __half g_xbc[(size_t)MROWS * CONVD];
__device__ __half g_y[(size_t)MROWS * DSSM];
__device__ __half g_states[(size_t)BATCH * NC64 * NH * HD * DS];
__device__ __half g_prev[(size_t)BATCH * NC64 * NH * HD * DS];
__device__ float g_cs[(size_t)BATCH * NC64 * NH * TCH];
__device__ float g_dt[(size_t)BATCH * NC64 * NH * TCH];
__device__ float g_scale[(size_t)BATCH * NC64 * NH];

__device__ __half g_uh[(size_t)MROWS * D_MODEL];
__device__ __half g_wih[(size_t)DIP * D_MODEL];
__device__ __half g_ynh[(size_t)MROWS * DSSM];
__device__ __half g_woh[(size_t)D_MODEL * DSSM];

// ---------------- helpers ----------------
struct alignas(8) half4 { __half a, b, c, d; };

__device__ __forceinline__ float fast_silu(float x) {
    float t;
    asm("tanh.approx.f32 %0, %1;" : "=f"(t) : "f"(x * 0.5f));
    return 0.5f * x * (1.f + t);
}

__device__ __forceinline__ void mma16816h(float* d, const uint32_t* a, const uint32_t* b) {
    asm volatile(
        "mma.sync.aligned.m16n8k16.row.col.f32.f16.f16.f32 "
        "{%0,%1,%2,%3}, {%4,%5,%6,%7}, {%8,%9}, {%0,%1,%2,%3};"
        : "+f"(d[0]), "+f"(d[1]), "+f"(d[2]), "+f"(d[3])
        : "r"(a[0]), "r"(a[1]), "r"(a[2]), "r"(a[3]), "r"(b[0]), "r"(b[1]));
}

__device__ __forceinline__ void ldsm_x4(uint32_t& r0, uint32_t& r1, uint32_t& r2,
                                        uint32_t& r3, uint32_t addr) {
    asm volatile("ldmatrix.sync.aligned.m8n8.x4.shared.b16 {%0,%1,%2,%3}, [%4];"
                 : "=r"(r0), "=r"(r1), "=r"(r2), "=r"(r3) : "r"(addr));
}

__device__ __forceinline__ void cpasync16(uint32_t dst, const void* src, int szvalid) {
    asm volatile("cp.async.cg.shared.global [%0], [%1], 16, %2;"
                 :: "r"(dst), "l"(src), "r"(szvalid) : "memory");
}
#define CPASYNC_COMMIT() asm volatile("cp.async.commit_group;" ::: "memory")
#define CPASYNC_WAIT(n)  asm volatile("cp.async.wait_group %0;" :: "n"(n) : "memory")

// ---------------- merged fp32 -> fp16 convert (3 tensors, one launch) ----------------
__global__ void convert_all_kernel(const float* __restrict__ a, __half* __restrict__ ao, int n1,
                                   const float* __restrict__ b, __half* __restrict__ bo, int n2,
                                   const float* __restrict__ c, __half* __restrict__ co, int n3) {
    int i = blockIdx.x * 256 + threadIdx.x;
    const float* src;
    __half* dst;
    if (i < n1) { src = a; dst = ao; }
    else if (i < n1 + n2) { src = b; dst = bo; i -= n1; }
    else if (i < n1 + n2 + n3) { src = c; dst = co; i -= n1 + n2; }
    else return;
    float4 v = ((const float4*)src)[i];
    half4 hv = {__float2half(v.x), __float2half(v.y),
                __float2half(v.z), __float2half(v.w)};
    ((half4*)dst)[i] = hv;
}

// ---------------- chunk scale precompute ----------------
__global__ void scale_kernel(const float* __restrict__ cs, float* __restrict__ scale, int n) {
    int i = blockIdx.x * 256 + threadIdx.x;
    if (i < n) scale[i] = __expf(cs[(size_t)i * TCH + TCH - 1]);
}

// ---------------- fp16 single-pass GEMM, one barrier per 2 k-steps ----------------
#define GK 16
#define GPAD 24
#define NSTAGE 4
#define GEMM_SMEM (NSTAGE * 2 * 128 * GPAD * 2)   // 49152 bytes

template <typename OutT>
__global__ __launch_bounds__(256, 2) void gemm_nt_fp16(
    const __half* __restrict__ A, const __half* __restrict__ B,
    OutT* __restrict__ C, int M, int N, int K) {
    extern __shared__ __half smh[];
    __half* sA = smh;
    __half* sB = smh + NSTAGE * 128 * GPAD;

    const int tid = threadIdx.x;
    const int wid = tid >> 5, lane = tid & 31;
    const int wm = wid >> 2, wn = wid & 3;
    const int grp = lane >> 2, q2 = (lane & 3) * 2;
    const int rowBase = blockIdx.y * 128;
    const int colBase = blockIdx.x * 128;
    const int lrow = tid >> 1;
    const int lkh = (tid & 1) * 8;

    const int lmRow = lane & 15;
    const int lmK = (lane >> 4) << 3;

    const uint32_t sA_s = (uint32_t)__cvta_generic_to_shared(sA);
    const uint32_t sB_s = (uint32_t)__cvta_generic_to_shared(sB);

    float acc[4][4][4];
#pragma unroll
    for (int i = 0; i < 4; i++)
#pragma unroll
        for (int j = 0; j < 4; j++)
#pragma unroll
            for (int r = 0; r < 4; r++) acc[i][j][r] = 0.f;

    const int nk = K / GK;
#define SIDX(st, r, k) ((((st) * 128 + (r)) * GPAD) + (k))

    const __half* pA = A + (size_t)(rowBase + lrow) * K + lkh;
    int cn = colBase + lrow;
    int bok = (cn < N) ? 16 : 0;
    int cnc = (cn < N) ? cn : 0;
    const __half* pB = B + (size_t)cnc * K + lkh;

    auto load_stage = [&](int st, int kc) {
        int ko = kc * GK;
        cpasync16(sA_s + SIDX(st, lrow, lkh) * 2, pA + ko, 16);
        cpasync16(sB_s + SIDX(st, lrow, lkh) * 2, pB + ko, bok);
        CPASYNC_COMMIT();
    };

    load_stage(0, 0);
    load_stage(1, 1);

    for (int k = 0; k < nk; k += 2) {
        CPASYNC_WAIT(0);      // this thread's loads for pair (k, k+1) done
        __syncthreads();      // publishes pair data; orders WAR for stages (k+2,k+3)%4
        if (k + 2 < nk) {
            load_stage((k + 2) & (NSTAGE - 1), k + 2);
            load_stage((k + 3) & (NSTAGE - 1), k + 3);
        }
#pragma unroll
        for (int kk = 0; kk < 2; kk++) {
            int st = (k + kk) & (NSTAGE - 1);
            uint32_t bb[4][2];
            {
                uint32_t r0, r1, r2, r3;
                ldsm_x4(r0, r1, r2, r3, sB_s + SIDX(st, wn * 32 + lmRow, lmK) * 2);
                bb[0][0] = r0; bb[0][1] = r2; bb[1][0] = r1; bb[1][1] = r3;
                ldsm_x4(r0, r1, r2, r3, sB_s + SIDX(st, wn * 32 + 16 + lmRow, lmK) * 2);
                bb[2][0] = r0; bb[2][1] = r2; bb[3][0] = r1; bb[3][1] = r3;
            }
#pragma unroll
            for (int mt = 0; mt < 4; mt++) {
                int r0row = wm * 64 + mt * 16;
                uint32_t aa[4];
                ldsm_x4(aa[0], aa[1], aa[2], aa[3], sA_s + SIDX(st, r0row + lmRow, lmK) * 2);
#pragma unroll
                for (int nt = 0; nt < 4; nt++) mma16816h(acc[mt][nt], aa, bb[nt]);
            }
        }
    }
#pragma unroll
    for (int mt = 0; mt < 4; mt++) {
#pragma unroll
        for (int nt = 0; nt < 4; nt++) {
            int colTile = colBase + wn * 32 + nt * 8;
            if (colTile >= N) continue;
            int r0 = rowBase + wm * 64 + mt * 16 + grp;
            int c0 = colTile + q2;
            if constexpr (sizeof(OutT) == 2) {
                *(__half2*)&C[(size_t)r0 * N + c0] =
                    __floats2half2_rn(acc[mt][nt][0], acc[mt][nt][1]);
                *(__half2*)&C[(size_t)(r0 + 8) * N + c0] =
                    __floats2half2_rn(acc[mt][nt][2], acc[mt][nt][3]);
            } else {
                *(float2*)&C[(size_t)r0 * N + c0] = make_float2(acc[mt][nt][0], acc[mt][nt][1]);
                *(float2*)&C[(size_t)(r0 + 8) * N + c0] = make_float2(acc[mt][nt][2], acc[mt][nt][3]);
            }
        }
    }
#undef SIDX
}

// ---------------- conv1d + SiLU : 4 t per thread, fp16 in/out ----------------
__global__ void conv_silu_kernel(const __half* __restrict__ zxh,
                                 const float* __restrict__ conv_w,
                                 const float* __restrict__ conv_b,
                                 __half* __restrict__ xbc) {
    size_t idx = (size_t)blockIdx.x * 256 + threadIdx.x;
    const size_t total = (size_t)(MROWS / 4) * CONVD;
    if (idx >= total) return;
    int cc = (int)(idx % CONVD);
    size_t r4 = idx / CONVD;
    size_t bt0 = r4 * 4;
    int t0 = (int)(bt0 % L_SEQ);

    float w0 = conv_w[cc * 4 + 0], w1 = conv_w[cc * 4 + 1];
    float w2 = conv_w[cc * 4 + 2], w3 = conv_w[cc * 4 + 3];
    float bia = conv_b[cc];

    float v[7];
#pragma unroll
    for (int j = 0; j < 7; j++) {
        int tt = t0 - 3 + j;
        v[j] = (tt >= 0) ? __half2float(zxh[(bt0 - 3 + j) * DIP + 2048 + cc]) : 0.f;
    }
#pragma unroll
    for (int i = 0; i < 4; i++) {
        float acc = bia;
        acc = fmaf(v[i + 0], w0, acc);
        acc = fmaf(v[i + 1], w1, acc);
        acc = fmaf(v[i + 2], w2, acc);
        acc = fmaf(v[i + 3], w3, acc);
        xbc[(bt0 + i) * CONVD + cc] = __float2half(fast_silu(acc));
    }
}

// ---------------- K1a: dt/cs + per-chunk states ----------------
#define SB_S 136
#define ST_S 66
#define SM_K1A_BYTES ((128 * ST_S + 64 * ST_S) * 2 + (2 * HPB * 64 + 64) * 4)

__global__ __launch_bounds__(256, 2) void ssm_states_kernel(
    const __half* __restrict__ zxh, const __half* __restrict__ xbc,
    const float* __restrict__ dt_bias, const float* __restrict__ A_log,
    __half* __restrict__ states, float* __restrict__ cs_out, float* __restrict__ dt_out) {
    extern __shared__ char smraw[];
    __half* sBT = (__half*)smraw;
    __half* sXd = sBT + 128 * ST_S;
    float* s_dt = (float*)(sXd + 64 * ST_S);
    float* s_cs = s_dt + HPB * 64;
    float* sEd = s_cs + HPB * 64;

    const int c = blockIdx.x, hg = blockIdx.y, b = blockIdx.z;
    const int h0 = hg * HPB;
    const int tid = threadIdx.x;
    const int wid = tid >> 5, lane = tid & 31;
    const int wm = wid >> 2, wn = wid & 3;
    const int grp = lane >> 2, q2 = (lane & 3) * 2;
    const int row0 = b * L_SEQ + c * TCH;
    const __half* xrow = xbc + (size_t)row0 * CONVD;

    {
        int h = h0 + wid;
        float Ah = -__expf(A_log[h]);
        float bias = dt_bias[h];
        float d0 = __half2float(zxh[(size_t)(row0 + lane) * DIP + 4352 + h]) + bias;
        float d1 = __half2float(zxh[(size_t)(row0 + 32 + lane) * DIP + 4352 + h]) + bias;
        float dt0 = (d0 > 20.f) ? d0 : log1pf(__expf(d0));
        float dt1 = (d1 > 20.f) ? d1 : log1pf(__expf(d1));
        s_dt[wid * 64 + lane] = dt0;
        s_dt[wid * 64 + 32 + lane] = dt1;
        float v0 = dt0 * Ah, v1 = dt1 * Ah;
#pragma unroll
        for (int off = 1; off < 32; off <<= 1) {
            float n0 = __shfl_up_sync(0xffffffffu, v0, off);
            float n1 = __shfl_up_sync(0xffffffffu, v1, off);
            if (lane >= off) { v0 += n0; v1 += n1; }
        }
        v1 += __shfl_sync(0xffffffffu, v0, 31);
        s_cs[wid * 64 + lane] = v0;
        s_cs[wid * 64 + 32 + lane] = v1;
        size_t cbase = (((size_t)b * NC64 + c) * NH + h) * TCH;
        cs_out[cbase + lane] = v0;
        cs_out[cbase + 32 + lane] = v1;
        dt_out[cbase + lane] = dt0;
        dt_out[cbase + 32 + lane] = dt1;
    }

    for (int idx = tid; idx < 64 * 128; idx += 256) {
        int s = idx >> 7, n = idx & 127;
        sBT[n * ST_S + s] = xrow[(size_t)s * CONVD + 2048 + n];
    }
    __syncthreads();

    for (int hl = 0; hl < HPB; hl++) {
        int h = h0 + hl;
        const float* csh = s_cs + hl * 64;
        const float* dth = s_dt + hl * 64;
        const float csL = csh[63];
        if (tid < 64) sEd[tid] = __expf(csL - csh[tid]);
        __syncthreads();
        for (int idx = tid; idx < 64 * 64; idx += 256) {
            int s = idx >> 6, p = idx & 63;
            float xv = __half2float(xrow[(size_t)s * CONVD + h * 64 + p]);
            sXd[p * ST_S + s] = __float2half(xv * dth[s] * sEd[s]);
        }
        __syncthreads();

        float st[2][4][4];
#pragma unroll
        for (int i = 0; i < 2; i++)
#pragma unroll
            for (int j = 0; j < 4; j++)
#pragma unroll
                for (int r = 0; r < 4; r++) st[i][j][r] = 0.f;
        for (int kb = 0; kb < 64; kb += 16) {
            uint32_t bb[4][2];
#pragma unroll
            for (int nt = 0; nt < 4; nt++) {
                int c0 = wn * 32 + nt * 8 + grp;
                bb[nt][0] = *(const uint32_t*)&sBT[c0 * ST_S + kb + q2];
                bb[nt][1] = *(const uint32_t*)&sBT[c0 * ST_S + kb + q2 + 8];
            }
#pragma unroll
            for (int mt = 0; mt < 2; mt++) {
                int r0 = wm * 32 + mt * 16 + grp;
                uint32_t aa[4];
                aa[0] = *(const uint32_t*)&sXd[r0 * ST_S + kb + q2];
                aa[1] = *(const uint32_t*)&sXd[(r0 + 8) * ST_S + kb + q2];
                aa[2] = *(const uint32_t*)&sXd[r0 * ST_S + kb + q2 + 8];
                aa[3] = *(const uint32_t*)&sXd[(r0 + 8) * ST_S + kb + q2 + 8];
#pragma unroll
                for (int nt = 0; nt < 4; nt++) mma16816h(st[mt][nt], aa, bb[nt]);
            }
        }
        size_t sbase = (((size_t)b * NC64 + c) * NH + h) * (size_t)(HD * DS);
#pragma unroll
        for (int mt = 0; mt < 2; mt++)
#pragma unroll
            for (int nt = 0; nt < 4; nt++) {
                int p0 = wm * 32 + mt * 16 + grp;
                int n0 = wn * 32 + nt * 8 + q2;
                *(__half2*)&states[sbase + (size_t)p0 * DS + n0] =
                    __floats2half2_rn(st[mt][nt][0], st[mt][nt][1]);
                *(__half2*)&states[sbase + (size_t)(p0 + 8) * DS + n0] =
                    __floats2half2_rn(st[mt][nt][2], st[mt][nt][3]);
            }
        __syncthreads();
    }
}

// ---------------- K2: inter-chunk recurrence (precomputed scales) ----------------
__global__ void chunk_scan64(const __half* __restrict__ states,
                             const float* __restrict__ scale,
                             __half* __restrict__ prev) {
    const int seg = blockIdx.x, h = blockIdx.y, b = blockIdx.z;
    const int e2 = seg * 256 + threadIdx.x;
    float2 P = make_float2(0.f, 0.f);
    for (int c = 0; c < NC64; c++) {
        size_t base = ((size_t)b * NC64 + c) * NH + h;
        float sc = __ldg(&scale[base]);
        size_t off = base * (size_t)(HD * DS / 2) + e2;
        ((__half2*)prev)[off] = __floats2half2_rn(P.x, P.y);
        float2 sv = __half22float2(((const __half2*)states)[off]);
        P.x = fmaf(P.x, sc, sv.x);
        P.y = fmaf(P.y, sc, sv.y);
    }
}

// ---------------- K1b: fused Y = Y_diag + Y_off + D*x, fp16 y write ----------------
#define SM_K1B_BYTES ((3 * 64 * SB_S + 2 * 64 * ST_S) * 2 + (64 * ST_S + 2 * 64) * 4)

__global__ __launch_bounds__(256, 2) void ssm_y_kernel(
    const __half* __restrict__ xbc, const __half* __restrict__ prev,
    const float* __restrict__ cs, const float* __restrict__ dt,
    const float* __restrict__ Dvec, __half* __restrict__ y) {
    extern __shared__ char smraw[];
    __half* sB = (__half*)smraw;
    __half* sC = sB + 64 * SB_S;
    __half* sP = sC + 64 * SB_S;
    __half* sGh = sP + 64 * SB_S;
    __half* sX = sGh + 64 * ST_S;
    float* sG = (float*)(sX + 64 * ST_S);
    float* s_cs = sG + 64 * ST_S;
    float* s_dt = s_cs + 64;

    const int c = blockIdx.x, hg = blockIdx.y, b = blockIdx.z;
    const int h0 = hg * HPB;
    const int tid = threadIdx.x;
    const int wid = tid >> 5, lane = tid & 31;
    const int wm = wid >> 2, wn = wid & 3;
    const int grp = lane >> 2, q2 = (lane & 3) * 2;
    const int row0 = b * L_SEQ + c * TCH;
    const __half* xrow = xbc + (size_t)row0 * CONVD;

    for (int idx = tid; idx < 64 * 128; idx += 256) {
        int s = idx >> 7, n = idx & 127;
        sB[s * SB_S + n] = xrow[(size_t)s * CONVD + 2048 + n];
        sC[s * SB_S + n] = xrow[(size_t)s * CONVD + 2176 + n];
    }
    __syncthreads();

    // G = C * B^T (head-independent)
    {
        float g[2][2][4];
#pragma unroll
        for (int i = 0; i < 2; i++)
#pragma unroll
            for (int j = 0; j < 2; j++)
#pragma unroll
                for (int r = 0; r < 4; r++) g[i][j][r] = 0.f;
        for (int kb = 0; kb < 128; kb += 16) {
            uint32_t bb[2][2];
#pragma unroll
            for (int nt = 0; nt < 2; nt++) {
                int c0 = wn * 16 + nt * 8 + grp;
                bb[nt][0] = *(const uint32_t*)&sB[c0 * SB_S + kb + q2];
                bb[nt][1] = *(const uint32_t*)&sB[c0 * SB_S + kb + q2 + 8];
            }
#pragma unroll
            for (int mt = 0; mt < 2; mt++) {
                int r0 = wm * 32 + mt * 16 + grp;
                uint32_t aa[4];
                aa[0] = *(const uint32_t*)&sC[r0 * SB_S + kb + q2];
                aa[1] = *(const uint32_t*)&sC[(r0 + 8) * SB_S + kb + q2];
                aa[2] = *(const uint32_t*)&sC[r0 * SB_S + kb + q2 + 8];
                aa[3] = *(const uint32_t*)&sC[(r0 + 8) * SB_S + kb + q2 + 8];
#pragma unroll
                for (int nt = 0; nt < 2; nt++) mma16816h(g[mt][nt], aa, bb[nt]);
            }
        }
#pragma unroll
        for (int mt = 0; mt < 2; mt++)
#pragma unroll
            for (int nt = 0; nt < 2; nt++) {
                int t = wm * 32 + mt * 16 + grp;
                int s = wn * 16 + nt * 8 + q2;
                *(float2*)&sG[t * ST_S + s] = make_float2(g[mt][nt][0], g[mt][nt][1]);
                *(float2*)&sG[(t + 8) * ST_S + s] = make_float2(g[mt][nt][2], g[mt][nt][3]);
            }
    }

    __syncthreads();
    for (int idx = tid; idx < 64 * 64; idx += 256) {
        int t = idx >> 6, s = idx & 63;
        if (t < s) sGh[t * ST_S + s] = __ushort_as_half(0);
    }

    for (int hl = 0; hl < HPB; hl++) {
        int h = h0 + hl;
        __syncthreads();
        size_t cbase = (((size_t)b * NC64 + c) * NH + h) * TCH;
        if (tid < 64) {
            s_cs[tid] = cs[cbase + tid];
            s_dt[tid] = dt[cbase + tid];
        }
        size_t pbase = (((size_t)b * NC64 + c) * NH + h) * (size_t)(HD * DS);
        for (int idx = tid; idx < 64 * 128; idx += 256) {
            int p = idx >> 7, n = idx & 127;
            sP[p * SB_S + n] = prev[pbase + (size_t)p * DS + n];
        }
        __syncthreads();
        for (int idx = tid; idx < 64 * 64; idx += 256) {
            int t = idx >> 6, s = idx & 63;
            if (t >= s) {
                sGh[t * ST_S + s] =
                    __float2half(sG[t * ST_S + s] * __expf(s_cs[t] - s_cs[s]));
            }
            int p = idx & 63, ss = idx >> 6;
            float xv = __half2float(xrow[(size_t)ss * CONVD + h * 64 + p]);
            sX[p * ST_S + ss] = __float2half(xv * s_dt[ss]);
        }
        __syncthreads();

        float yd[2][2][4], yo[2][2][4];
#pragma unroll
        for (int i = 0; i < 2; i++)
#pragma unroll
            for (int j = 0; j < 2; j++)
#pragma unroll
                for (int r = 0; r < 4; r++) { yd[i][j][r] = 0.f; yo[i][j][r] = 0.f; }
        for (int kb = 0; kb < 64; kb += 16) {
            uint32_t bb[2][2];
#pragma unroll
            for (int nt = 0; nt < 2; nt++) {
                int c0 = wn * 16 + nt * 8 + grp;
                bb[nt][0] = *(const uint32_t*)&sX[c0 * ST_S + kb + q2];
                bb[nt][1] = *(const uint32_t*)&sX[c0 * ST_S + kb + q2 + 8];
            }
#pragma unroll
            for (int mt = 0; mt < 2; mt++) {
                int r0 = wm * 32 + mt * 16 + grp;
                uint32_t aa[4];
                aa[0] = *(const uint32_t*)&sGh[r0 * ST_S + kb + q2];
                aa[1] = *(const uint32_t*)&sGh[(r0 + 8) * ST_S + kb + q2];
                aa[2] = *(const uint32_t*)&sGh[r0 * ST_S + kb + q2 + 8];
                aa[3] = *(const uint32_t*)&sGh[(r0 + 8) * ST_S + kb + q2 + 8];
#pragma unroll
                for (int nt = 0; nt < 2; nt++) mma16816h(yd[mt][nt], aa, bb[nt]);
            }
        }
        for (int kb = 0; kb < 128; kb += 16) {
            uint32_t bb[2][2];
#pragma unroll
            for (int nt = 0; nt < 2; nt++) {
                int c0 = wn * 16 + nt * 8 + grp;
                bb[nt][0] = *(const uint32_t*)&sP[c0 * SB_S + kb + q2];
                bb[nt][1] = *(const uint32_t*)&sP[c0 * SB_S + kb + q2 + 8];
            }
#pragma unroll
            for (int mt = 0; mt < 2; mt++) {
                int r0 = wm * 32 + mt * 16 + grp;
                uint32_t aa[4];
                aa[0] = *(const uint32_t*)&sC[r0 * SB_S + kb + q2];
                aa[1] = *(const uint32_t*)&sC[(r0 + 8) * SB_S + kb + q2];
                aa[2] = *(const uint32_t*)&sC[r0 * SB_S + kb + q2 + 8];
                aa[3] = *(const uint32_t*)&sC[(r0 + 8) * SB_S + kb + q2 + 8];
#pragma unroll
                for (int nt = 0; nt < 2; nt++) mma16816h(yo[mt][nt], aa, bb[nt]);
            }
        }

        float Dh = Dvec[h];
        float eT[2][2];
#pragma unroll
        for (int mt = 0; mt < 2; mt++)
#pragma unroll
            for (int rr = 0; rr < 2; rr++)
                eT[mt][rr] = __expf(s_cs[wm * 32 + mt * 16 + grp + rr * 8]);
#pragma unroll
        for (int mt = 0; mt < 2; mt++)
#pragma unroll
            for (int nt = 0; nt < 2; nt++) {
                int t0 = wm * 32 + mt * 16 + grp;
                int p0 = wn * 16 + nt * 8 + q2;
#pragma unroll
                for (int rr = 0; rr < 2; rr++) {
                    int t = t0 + rr * 8;
                    float e = eT[mt][rr];
                    __half2 xv2 = *(const __half2*)&xrow[(size_t)t * CONVD + h * 64 + p0];
                    float2 xv = __half22float2(xv2);
                    float ox = fmaf(e, yo[mt][nt][rr * 2 + 0], fmaf(Dh, xv.x, yd[mt][nt][rr * 2 + 0]));
                    float oy = fmaf(e, yo[mt][nt][rr * 2 + 1], fmaf(Dh, xv.y, yd[mt][nt][rr * 2 + 1]));
                    *(__half2*)&y[(size_t)(row0 + t) * DSSM + h * 64 + p0] =
                        __floats2half2_rn(ox, oy);
                }
            }
    }
}

// ---------------- gate (y * silu(z)) + RMSNorm -> fp16 ----------------
__global__ void gate_norm_kernel(const __half* __restrict__ zxh,
                                 const __half* __restrict__ y,
                                 const float* __restrict__ norm_w,
                                 __half* __restrict__ ynh) {
    const int row = blockIdx.x;
    const int tid = threadIdx.x;
    const __half* yrow = y + (size_t)row * DSSM;
    const __half* zrow = zxh + (size_t)row * DIP;
    float v[8];
    float ss = 0.f;
#pragma unroll
    for (int k = 0; k < 8; k++) {
        int e = tid + k * 256;
        float z = __half2float(zrow[e]);
        float vv = __half2float(yrow[e]) * fast_silu(z);
        v[k] = vv;
        ss = fmaf(vv, vv, ss);
    }
    __shared__ float red[256];
    red[tid] = ss;
    __syncthreads();
    for (int s = 128; s > 0; s >>= 1) {
        if (tid < s) red[tid] += red[tid + s];
        __syncthreads();
    }
    float r = rsqrtf(red[0] / (float)DSSM + 1e-5f);
#pragma unroll
    for (int k = 0; k < 8; k++) {
        int e = tid + k * 256;
        ynh[(size_t)row * DSSM + e] = __float2half(v[k] * r * norm_w[e]);
    }
}

// ---------------- host launch ----------------
extern "C" void kernel_launch(void* const* d_in, const int* in_sizes, int n_in,
                              void* d_out, int out_size) {
    const float* u       = (const float*)d_in[0];
    const float* W_in    = (const float*)d_in[1];
    const float* conv_w  = (const float*)d_in[2];
    const float* conv_b  = (const float*)d_in[3];
    const float* dt_bias = (const float*)d_in[4];
    const float* A_log   = (const float*)d_in[5];
    const float* Dv      = (const float*)d_in[6];
    const float* norm_w  = (const float*)d_in[7];
    const float* W_out   = (const float*)d_in[8];
    float* out = (float*)d_out;

    void *p_zxh, *p_xbc, *p_y, *p_states, *p_prev, *p_cs, *p_dt, *p_scale;
    void *p_uh, *p_wih, *p_ynh, *p_woh;
    cudaGetSymbolAddress(&p_zxh, g_zxh);
    cudaGetSymbolAddress(&p_xbc, g_xbc);
    cudaGetSymbolAddress(&p_y, g_y);
    cudaGetSymbolAddress(&p_states, g_states);
    cudaGetSymbolAddress(&p_prev, g_prev);
    cudaGetSymbolAddress(&p_cs, g_cs);
    cudaGetSymbolAddress(&p_dt, g_dt);
    cudaGetSymbolAddress(&p_scale, g_scale);
    cudaGetSymbolAddress(&p_uh, g_uh);
    cudaGetSymbolAddress(&p_wih, g_wih);
    cudaGetSymbolAddress(&p_ynh, g_ynh);
    cudaGetSymbolAddress(&p_woh, g_woh);
    __half* zxh = (__half*)p_zxh;
    __half* xbc = (__half*)p_xbc;
    __half* y = (__half*)p_y;
    __half* states = (__half*)p_states;
    __half* prev = (__half*)p_prev;
    float* cs = (float*)p_cs;
    float* dtb = (float*)p_dt;
    float* scale = (float*)p_scale;
    __half* uh = (__half*)p_uh;
    __half* wih = (__half*)p_wih;
    __half* ynh = (__half*)p_ynh;
    __half* woh = (__half*)p_woh;

    cudaFuncSetAttribute(gemm_nt_fp16<__half>, cudaFuncAttributeMaxDynamicSharedMemorySize,
                         GEMM_SMEM);
    cudaFuncSetAttribute(gemm_nt_fp16<float>, cudaFuncAttributeMaxDynamicSharedMemorySize,
                         GEMM_SMEM);
    cudaFuncSetAttribute(ssm_states_kernel, cudaFuncAttributeMaxDynamicSharedMemorySize,
                         SM_K1A_BYTES);
    cudaFuncSetAttribute(ssm_y_kernel, cudaFuncAttributeMaxDynamicSharedMemorySize,
                         SM_K1B_BYTES);

    // 0. fp16 conversions (one launch)
    {
        int n1 = MROWS * D_MODEL / 4;
        int n2 = DIP * D_MODEL / 4;
        int n3 = D_MODEL * DSSM / 4;
        int total = n1 + n2 + n3;
        convert_all_kernel<<<(total + 255) / 256, 256>>>(u, uh, n1, W_in, wih, n2,
                                                         W_out, woh, n3);
    }

    // 1. in_proj (fp16, fp16 output)
    gemm_nt_fp16<__half><<<dim3((DIP + 127) / 128, MROWS / 128), 256, GEMM_SMEM>>>(
        uh, wih, zxh, MROWS, DIP, D_MODEL);

    // 2. conv1d + silu -> fp16
    {
        size_t total4 = (size_t)(MROWS / 4) * CONVD;
        conv_silu_kernel<<<(unsigned)((total4 + 255) / 256), 256>>>(zxh, conv_w, conv_b, xbc);
    }

    // 3a. states + dt/cs
    ssm_states_kernel<<<dim3(NC64, NH / HPB, BATCH), 256, SM_K1A_BYTES>>>(
        zxh, xbc, dt_bias, A_log, states, cs, dtb);

    // 3b. per-chunk scale precompute + inter-chunk recurrence
    scale_kernel<<<(BATCH * NC64 * NH + 255) / 256, 256>>>(cs, scale, BATCH * NC64 * NH);
    chunk_scan64<<<dim3(16, NH, BATCH), 256>>>(states, scale, prev);

    // 3c. fused Y (Y_diag + Y_off + D*x), fp16 write
    ssm_y_kernel<<<dim3(NC64, NH / HPB, BATCH), 256, SM_K1B_BYTES>>>(
        xbc, prev, cs, dtb, Dv, y);

    // 4. gate + RMSNorm -> fp16
    gate_norm_kernel<<<MROWS, 256>>>(zxh, y, norm_w, ynh);

    // 5. out_proj (fp16, fp32 output)
    gemm_nt_fp16<float><<<dim3(D_MODEL / 128, MROWS / 128), 256, GEMM_SMEM>>>(
        ynh, woh, out, MROWS, D_MODEL, DSSM);
}

// round 16
// speedup vs baseline: 1.0859x; 1.0859x over previous
#include <cuda_runtime.h>
#include <cuda_bf16.h>
#include <cuda_fp16.h>
#include <math.h>
#include <stdint.h>

#define BATCH 2
#define L_SEQ 4096
#define D_MODEL 1024
#define DIP 4384          // D_IN_PROJ
#define DSSM 2048
#define CONVD 2304        // CONV_DIM
#define NH 32
#define HD 64
#define DS 128
#define NC64 64           // chunks of 64 per batch
#define TCH 64
#define HPB 8             // heads per block
#define MROWS (BATCH * L_SEQ)   // 8192

// ---------------- scratch (device globals; no allocation) ----------------
__device__ __half g_zxh[(size_t)MROWS * DIP];
__device__ __half g_xbc[(size_t)MROWS * CONVD];
__device__ __half g_y[(size_t)MROWS * DSSM];
__device__ __half g_states[(size_t)BATCH * NC64 * NH * HD * DS];
__device__ __half g_prev[(size_t)BATCH * NC64 * NH * HD * DS];
__device__ float g_cs[(size_t)BATCH * NC64 * NH * TCH];
__device__ float g_dt[(size_t)BATCH * NC64 * NH * TCH];
__device__ float g_scale[(size_t)BATCH * NC64 * NH];

__device__ __half g_uh[(size_t)MROWS * D_MODEL];
__device__ __half g_wih[(size_t)DIP * D_MODEL];
__device__ __half g_ynh[(size_t)MROWS * DSSM];
__device__ __half g_woh[(size_t)D_MODEL * DSSM];

// ---------------- helpers ----------------
struct alignas(8) half4 { __half a, b, c, d; };

__device__ __forceinline__ float fast_silu(float x) {
    float t;
    asm("tanh.approx.f32 %0, %1;" : "=f"(t) : "f"(x * 0.5f));
    return 0.5f * x * (1.f + t);
}

__device__ __forceinline__ void mma16816h(float* d, const uint32_t* a, const uint32_t* b) {
    asm volatile(
        "mma.sync.aligned.m16n8k16.row.col.f32.f16.f16.f32 "
        "{%0,%1,%2,%3}, {%4,%5,%6,%7}, {%8,%9}, {%0,%1,%2,%3};"
        : "+f"(d[0]), "+f"(d[1]), "+f"(d[2]), "+f"(d[3])
        : "r"(a[0]), "r"(a[1]), "r"(a[2]), "r"(a[3]), "r"(b[0]), "r"(b[1]));
}

__device__ __forceinline__ void ldsm_x4(uint32_t& r0, uint32_t& r1, uint32_t& r2,
                                        uint32_t& r3, uint32_t addr) {
    asm volatile("ldmatrix.sync.aligned.m8n8.x4.shared.b16 {%0,%1,%2,%3}, [%4];"
                 : "=r"(r0), "=r"(r1), "=r"(r2), "=r"(r3) : "r"(addr));
}

__device__ __forceinline__ void cpasync16(uint32_t dst, const void* src, int szvalid) {
    asm volatile("cp.async.cg.shared.global [%0], [%1], 16, %2;"
                 :: "r"(dst), "l"(src), "r"(szvalid) : "memory");
}
#define CPASYNC_COMMIT() asm volatile("cp.async.commit_group;" ::: "memory")
#define CPASYNC_WAIT(n)  asm volatile("cp.async.wait_group %0;" :: "n"(n) : "memory")

// ---------------- merged fp32 -> fp16 convert (3 tensors, one launch) ----------------
__global__ void convert_all_kernel(const float* __restrict__ a, __half* __restrict__ ao, int n1,
                                   const float* __restrict__ b, __half* __restrict__ bo, int n2,
                                   const float* __restrict__ c, __half* __restrict__ co, int n3) {
    int i = blockIdx.x * 256 + threadIdx.x;
    const float* src;
    __half* dst;
    if (i < n1) { src = a; dst = ao; }
    else if (i < n1 + n2) { src = b; dst = bo; i -= n1; }
    else if (i < n1 + n2 + n3) { src = c; dst = co; i -= n1 + n2; }
    else return;
    float4 v = ((const float4*)src)[i];
    half4 hv = {__float2half(v.x), __float2half(v.y),
                __float2half(v.z), __float2half(v.w)};
    ((half4*)dst)[i] = hv;
}

// ---------------- chunk scale precompute ----------------
__global__ void scale_kernel(const float* __restrict__ cs, float* __restrict__ scale, int n) {
    int i = blockIdx.x * 256 + threadIdx.x;
    if (i < n) scale[i] = __expf(cs[(size_t)i * TCH + TCH - 1]);
}

// ---------------- fp16 single-pass GEMM (R14 pipeline: WAIT(2), 1 barrier/k) ----------------
#define GK 16
#define GPAD 24
#define NSTAGE 4
#define GEMM_SMEM (NSTAGE * 2 * 128 * GPAD * 2)   // 49152 bytes

template <typename OutT>
__global__ __launch_bounds__(256, 2) void gemm_nt_fp16(
    const __half* __restrict__ A, const __half* __restrict__ B,
    OutT* __restrict__ C, int M, int N, int K) {
    extern __shared__ __half smh[];
    __half* sA = smh;
    __half* sB = smh + NSTAGE * 128 * GPAD;

    const int tid = threadIdx.x;
    const int wid = tid >> 5, lane = tid & 31;
    const int wm = wid >> 2, wn = wid & 3;
    const int grp = lane >> 2, q2 = (lane & 3) * 2;
    const int rowBase = blockIdx.y * 128;
    const int colBase = blockIdx.x * 128;
    const int lrow = tid >> 1;
    const int lkh = (tid & 1) * 8;

    const int lmRow = lane & 15;
    const int lmK = (lane >> 4) << 3;

    const uint32_t sA_s = (uint32_t)__cvta_generic_to_shared(sA);
    const uint32_t sB_s = (uint32_t)__cvta_generic_to_shared(sB);

    float acc[4][4][4];
#pragma unroll
    for (int i = 0; i < 4; i++)
#pragma unroll
        for (int j = 0; j < 4; j++)
#pragma unroll
            for (int r = 0; r < 4; r++) acc[i][j][r] = 0.f;

    const int nk = K / GK;
#define SIDX(st, r, k) ((((st) * 128 + (r)) * GPAD) + (k))

    const __half* pA = A + (size_t)(rowBase + lrow) * K + lkh;
    int cn = colBase + lrow;
    int bok = (cn < N) ? 16 : 0;
    int cnc = (cn < N) ? cn : 0;
    const __half* pB = B + (size_t)cnc * K + lkh;

    auto load_stage = [&](int st, int kc) {
        int ko = kc * GK;
        cpasync16(sA_s + SIDX(st, lrow, lkh) * 2, pA + ko, 16);
        cpasync16(sB_s + SIDX(st, lrow, lkh) * 2, pB + ko, bok);
        CPASYNC_COMMIT();
    };

    load_stage(0, 0);
    if (nk > 1) load_stage(1, 1);

    for (int k = 0; k < nk; k++) {
        int st = k & (NSTAGE - 1);
        if (k + 2 < nk) {
            load_stage((k + 2) & (NSTAGE - 1), k + 2);
            CPASYNC_WAIT(2);
        } else if (k + 1 < nk) {
            CPASYNC_WAIT(1);
        } else {
            CPASYNC_WAIT(0);
        }
        __syncthreads();   // single barrier per k-step (4-stage ring)

        uint32_t bb[4][2];
        {
            uint32_t r0, r1, r2, r3;
            ldsm_x4(r0, r1, r2, r3, sB_s + SIDX(st, wn * 32 + lmRow, lmK) * 2);
            bb[0][0] = r0; bb[0][1] = r2; bb[1][0] = r1; bb[1][1] = r3;
            ldsm_x4(r0, r1, r2, r3, sB_s + SIDX(st, wn * 32 + 16 + lmRow, lmK) * 2);
            bb[2][0] = r0; bb[2][1] = r2; bb[3][0] = r1; bb[3][1] = r3;
        }
#pragma unroll
        for (int mt = 0; mt < 4; mt++) {
            int r0row = wm * 64 + mt * 16;
            uint32_t aa[4];
            ldsm_x4(aa[0], aa[1], aa[2], aa[3], sA_s + SIDX(st, r0row + lmRow, lmK) * 2);
#pragma unroll
            for (int nt = 0; nt < 4; nt++) mma16816h(acc[mt][nt], aa, bb[nt]);
        }
    }
#pragma unroll
    for (int mt = 0; mt < 4; mt++) {
#pragma unroll
        for (int nt = 0; nt < 4; nt++) {
            int colTile = colBase + wn * 32 + nt * 8;
            if (colTile >= N) continue;
            int r0 = rowBase + wm * 64 + mt * 16 + grp;
            int c0 = colTile + q2;
            if constexpr (sizeof(OutT) == 2) {
                *(__half2*)&C[(size_t)r0 * N + c0] =
                    __floats2half2_rn(acc[mt][nt][0], acc[mt][nt][1]);
                *(__half2*)&C[(size_t)(r0 + 8) * N + c0] =
                    __floats2half2_rn(acc[mt][nt][2], acc[mt][nt][3]);
            } else {
                *(float2*)&C[(size_t)r0 * N + c0] = make_float2(acc[mt][nt][0], acc[mt][nt][1]);
                *(float2*)&C[(size_t)(r0 + 8) * N + c0] = make_float2(acc[mt][nt][2], acc[mt][nt][3]);
            }
        }
    }
#undef SIDX
}

// ---------------- conv1d + SiLU : 4 t per thread, fp16 in/out ----------------
__global__ void conv_silu_kernel(const __half* __restrict__ zxh,
                                 const float* __restrict__ conv_w,
                                 const float* __restrict__ conv_b,
                                 __half* __restrict__ xbc) {
    size_t idx = (size_t)blockIdx.x * 256 + threadIdx.x;
    const size_t total = (size_t)(MROWS / 4) * CONVD;
    if (idx >= total) return;
    int cc = (int)(idx % CONVD);
    size_t r4 = idx / CONVD;
    size_t bt0 = r4 * 4;
    int t0 = (int)(bt0 % L_SEQ);

    float w0 = conv_w[cc * 4 + 0], w1 = conv_w[cc * 4 + 1];
    float w2 = conv_w[cc * 4 + 2], w3 = conv_w[cc * 4 + 3];
    float bia = conv_b[cc];

    float v[7];
#pragma unroll
    for (int j = 0; j < 7; j++) {
        int tt = t0 - 3 + j;
        v[j] = (tt >= 0) ? __half2float(zxh[(bt0 - 3 + j) * DIP + 2048 + cc]) : 0.f;
    }
#pragma unroll
    for (int i = 0; i < 4; i++) {
        float acc = bia;
        acc = fmaf(v[i + 0], w0, acc);
        acc = fmaf(v[i + 1], w1, acc);
        acc = fmaf(v[i + 2], w2, acc);
        acc = fmaf(v[i + 3], w3, acc);
        xbc[(bt0 + i) * CONVD + cc] = __float2half(fast_silu(acc));
    }
}

// ---------------- K1a: dt/cs + per-chunk states ----------------
#define SB_S 136
#define ST_S 66
#define SM_K1A_BYTES ((128 * ST_S + 64 * ST_S) * 2 + (2 * HPB * 64 + 64) * 4)

__global__ __launch_bounds__(256, 2) void ssm_states_kernel(
    const __half* __restrict__ zxh, const __half* __restrict__ xbc,
    const float* __restrict__ dt_bias, const float* __restrict__ A_log,
    __half* __restrict__ states, float* __restrict__ cs_out, float* __restrict__ dt_out) {
    extern __shared__ char smraw[];
    __half* sBT = (__half*)smraw;
    __half* sXd = sBT + 128 * ST_S;
    float* s_dt = (float*)(sXd + 64 * ST_S);
    float* s_cs = s_dt + HPB * 64;
    float* sEd = s_cs + HPB * 64;

    const int c = blockIdx.x, hg = blockIdx.y, b = blockIdx.z;
    const int h0 = hg * HPB;
    const int tid = threadIdx.x;
    const int wid = tid >> 5, lane = tid & 31;
    const int wm = wid >> 2, wn = wid & 3;
    const int grp = lane >> 2, q2 = (lane & 3) * 2;
    const int row0 = b * L_SEQ + c * TCH;
    const __half* xrow = xbc + (size_t)row0 * CONVD;

    {
        int h = h0 + wid;
        float Ah = -__expf(A_log[h]);
        float bias = dt_bias[h];
        float d0 = __half2float(zxh[(size_t)(row0 + lane) * DIP + 4352 + h]) + bias;
        float d1 = __half2float(zxh[(size_t)(row0 + 32 + lane) * DIP + 4352 + h]) + bias;
        float dt0 = (d0 > 20.f) ? d0 : log1pf(__expf(d0));
        float dt1 = (d1 > 20.f) ? d1 : log1pf(__expf(d1));
        s_dt[wid * 64 + lane] = dt0;
        s_dt[wid * 64 + 32 + lane] = dt1;
        float v0 = dt0 * Ah, v1 = dt1 * Ah;
#pragma unroll
        for (int off = 1; off < 32; off <<= 1) {
            float n0 = __shfl_up_sync(0xffffffffu, v0, off);
            float n1 = __shfl_up_sync(0xffffffffu, v1, off);
            if (lane >= off) { v0 += n0; v1 += n1; }
        }
        v1 += __shfl_sync(0xffffffffu, v0, 31);
        s_cs[wid * 64 + lane] = v0;
        s_cs[wid * 64 + 32 + lane] = v1;
        size_t cbase = (((size_t)b * NC64 + c) * NH + h) * TCH;
        cs_out[cbase + lane] = v0;
        cs_out[cbase + 32 + lane] = v1;
        dt_out[cbase + lane] = dt0;
        dt_out[cbase + 32 + lane] = dt1;
    }

    for (int idx = tid; idx < 64 * 128; idx += 256) {
        int s = idx >> 7, n = idx & 127;
        sBT[n * ST_S + s] = xrow[(size_t)s * CONVD + 2048 + n];
    }
    __syncthreads();

    for (int hl = 0; hl < HPB; hl++) {
        int h = h0 + hl;
        const float* csh = s_cs + hl * 64;
        const float* dth = s_dt + hl * 64;
        const float csL = csh[63];
        if (tid < 64) sEd[tid] = __expf(csL - csh[tid]);
        __syncthreads();
        for (int idx = tid; idx < 64 * 64; idx += 256) {
            int s = idx >> 6, p = idx & 63;
            float xv = __half2float(xrow[(size_t)s * CONVD + h * 64 + p]);
            sXd[p * ST_S + s] = __float2half(xv * dth[s] * sEd[s]);
        }
        __syncthreads();

        float st[2][4][4];
#pragma unroll
        for (int i = 0; i < 2; i++)
#pragma unroll
            for (int j = 0; j < 4; j++)
#pragma unroll
                for (int r = 0; r < 4; r++) st[i][j][r] = 0.f;
        for (int kb = 0; kb < 64; kb += 16) {
            uint32_t bb[4][2];
#pragma unroll
            for (int nt = 0; nt < 4; nt++) {
                int c0 = wn * 32 + nt * 8 + grp;
                bb[nt][0] = *(const uint32_t*)&sBT[c0 * ST_S + kb + q2];
                bb[nt][1] = *(const uint32_t*)&sBT[c0 * ST_S + kb + q2 + 8];
            }
#pragma unroll
            for (int mt = 0; mt < 2; mt++) {
                int r0 = wm * 32 + mt * 16 + grp;
                uint32_t aa[4];
                aa[0] = *(const uint32_t*)&sXd[r0 * ST_S + kb + q2];
                aa[1] = *(const uint32_t*)&sXd[(r0 + 8) * ST_S + kb + q2];
                aa[2] = *(const uint32_t*)&sXd[r0 * ST_S + kb + q2 + 8];
                aa[3] = *(const uint32_t*)&sXd[(r0 + 8) * ST_S + kb + q2 + 8];
#pragma unroll
                for (int nt = 0; nt < 4; nt++) mma16816h(st[mt][nt], aa, bb[nt]);
            }
        }
        size_t sbase = (((size_t)b * NC64 + c) * NH + h) * (size_t)(HD * DS);
#pragma unroll
        for (int mt = 0; mt < 2; mt++)
#pragma unroll
            for (int nt = 0; nt < 4; nt++) {
                int p0 = wm * 32 + mt * 16 + grp;
                int n0 = wn * 32 + nt * 8 + q2;
                *(__half2*)&states[sbase + (size_t)p0 * DS + n0] =
                    __floats2half2_rn(st[mt][nt][0], st[mt][nt][1]);
                *(__half2*)&states[sbase + (size_t)(p0 + 8) * DS + n0] =
                    __floats2half2_rn(st[mt][nt][2], st[mt][nt][3]);
            }
        __syncthreads();
    }
}

// ---------------- K2: inter-chunk recurrence (precomputed scales) ----------------
__global__ void chunk_scan64(const __half* __restrict__ states,
                             const float* __restrict__ scale,
                             __half* __restrict__ prev) {
    const int seg = blockIdx.x, h = blockIdx.y, b = blockIdx.z;
    const int e2 = seg * 256 + threadIdx.x;
    float2 P = make_float2(0.f, 0.f);
    for (int c = 0; c < NC64; c++) {
        size_t base = ((size_t)b * NC64 + c) * NH + h;
        float sc = __ldg(&scale[base]);
        size_t off = base * (size_t)(HD * DS / 2) + e2;
        ((__half2*)prev)[off] = __floats2half2_rn(P.x, P.y);
        float2 sv = __half22float2(((const __half2*)states)[off]);
        P.x = fmaf(P.x, sc, sv.x);
        P.y = fmaf(P.y, sc, sv.y);
    }
}

// ---------------- K1b: fused Y = Y_diag + Y_off + D*x, fp16 y write ----------------
#define SM_K1B_BYTES ((3 * 64 * SB_S + 2 * 64 * ST_S) * 2 + (64 * ST_S + 2 * 64) * 4)

__global__ __launch_bounds__(256, 2) void ssm_y_kernel(
    const __half* __restrict__ xbc, const __half* __restrict__ prev,
    const float* __restrict__ cs, const float* __restrict__ dt,
    const float* __restrict__ Dvec, __half* __restrict__ y) {
    extern __shared__ char smraw[];
    __half* sB = (__half*)smraw;
    __half* sC = sB + 64 * SB_S;
    __half* sP = sC + 64 * SB_S;
    __half* sGh = sP + 64 * SB_S;
    __half* sX = sGh + 64 * ST_S;
    float* sG = (float*)(sX + 64 * ST_S);
    float* s_cs = sG + 64 * ST_S;
    float* s_dt = s_cs + 64;

    const int c = blockIdx.x, hg = blockIdx.y, b = blockIdx.z;
    const int h0 = hg * HPB;
    const int tid = threadIdx.x;
    const int wid = tid >> 5, lane = tid & 31;
    const int wm = wid >> 2, wn = wid & 3;
    const int grp = lane >> 2, q2 = (lane & 3) * 2;
    const int row0 = b * L_SEQ + c * TCH;
    const __half* xrow = xbc + (size_t)row0 * CONVD;

    for (int idx = tid; idx < 64 * 128; idx += 256) {
        int s = idx >> 7, n = idx & 127;
        sB[s * SB_S + n] = xrow[(size_t)s * CONVD + 2048 + n];
        sC[s * SB_S + n] = xrow[(size_t)s * CONVD + 2176 + n];
    }
    __syncthreads();

    // G = C * B^T (head-independent)
    {
        float g[2][2][4];
#pragma unroll
        for (int i = 0; i < 2; i++)
#pragma unroll
            for (int j = 0; j < 2; j++)
#pragma unroll
                for (int r = 0; r < 4; r++) g[i][j][r] = 0.f;
        for (int kb = 0; kb < 128; kb += 16) {
            uint32_t bb[2][2];
#pragma unroll
            for (int nt = 0; nt < 2; nt++) {
                int c0 = wn * 16 + nt * 8 + grp;
                bb[nt][0] = *(const uint32_t*)&sB[c0 * SB_S + kb + q2];
                bb[nt][1] = *(const uint32_t*)&sB[c0 * SB_S + kb + q2 + 8];
            }
#pragma unroll
            for (int mt = 0; mt < 2; mt++) {
                int r0 = wm * 32 + mt * 16 + grp;
                uint32_t aa[4];
                aa[0] = *(const uint32_t*)&sC[r0 * SB_S + kb + q2];
                aa[1] = *(const uint32_t*)&sC[(r0 + 8) * SB_S + kb + q2];
                aa[2] = *(const uint32_t*)&sC[r0 * SB_S + kb + q2 + 8];
                aa[3] = *(const uint32_t*)&sC[(r0 + 8) * SB_S + kb + q2 + 8];
#pragma unroll
                for (int nt = 0; nt < 2; nt++) mma16816h(g[mt][nt], aa, bb[nt]);
            }
        }
#pragma unroll
        for (int mt = 0; mt < 2; mt++)
#pragma unroll
            for (int nt = 0; nt < 2; nt++) {
                int t = wm * 32 + mt * 16 + grp;
                int s = wn * 16 + nt * 8 + q2;
                *(float2*)&sG[t * ST_S + s] = make_float2(g[mt][nt][0], g[mt][nt][1]);
                *(float2*)&sG[(t + 8) * ST_S + s] = make_float2(g[mt][nt][2], g[mt][nt][3]);
            }
    }

    __syncthreads();
    for (int idx = tid; idx < 64 * 64; idx += 256) {
        int t = idx >> 6, s = idx & 63;
        if (t < s) sGh[t * ST_S + s] = __ushort_as_half(0);
    }

    for (int hl = 0; hl < HPB; hl++) {
        int h = h0 + hl;
        __syncthreads();
        size_t cbase = (((size_t)b * NC64 + c) * NH + h) * TCH;
        if (tid < 64) {
            s_cs[tid] = cs[cbase + tid];
            s_dt[tid] = dt[cbase + tid];
        }
        size_t pbase = (((size_t)b * NC64 + c) * NH + h) * (size_t)(HD * DS);
        for (int idx = tid; idx < 64 * 128; idx += 256) {
            int p = idx >> 7, n = idx & 127;
            sP[p * SB_S + n] = prev[pbase + (size_t)p * DS + n];
        }
        __syncthreads();
        for (int idx = tid; idx < 64 * 64; idx += 256) {
            int t = idx >> 6, s = idx & 63;
            if (t >= s) {
                sGh[t * ST_S + s] =
                    __float2half(sG[t * ST_S + s] * __expf(s_cs[t] - s_cs[s]));
            }
            int p = idx & 63, ss = idx >> 6;
            float xv = __half2float(xrow[(size_t)ss * CONVD + h * 64 + p]);
            sX[p * ST_S + ss] = __float2half(xv * s_dt[ss]);
        }
        __syncthreads();

        float yd[2][2][4], yo[2][2][4];
#pragma unroll
        for (int i = 0; i < 2; i++)
#pragma unroll
            for (int j = 0; j < 2; j++)
#pragma unroll
                for (int r = 0; r < 4; r++) { yd[i][j][r] = 0.f; yo[i][j][r] = 0.f; }
        for (int kb = 0; kb < 64; kb += 16) {
            uint32_t bb[2][2];
#pragma unroll
            for (int nt = 0; nt < 2; nt++) {
                int c0 = wn * 16 + nt * 8 + grp;
                bb[nt][0] = *(const uint32_t*)&sX[c0 * ST_S + kb + q2];
                bb[nt][1] = *(const uint32_t*)&sX[c0 * ST_S + kb + q2 + 8];
            }
#pragma unroll
            for (int mt = 0; mt < 2; mt++) {
                int r0 = wm * 32 + mt * 16 + grp;
                uint32_t aa[4];
                aa[0] = *(const uint32_t*)&sGh[r0 * ST_S + kb + q2];
                aa[1] = *(const uint32_t*)&sGh[(r0 + 8) * ST_S + kb + q2];
                aa[2] = *(const uint32_t*)&sGh[r0 * ST_S + kb + q2 + 8];
                aa[3] = *(const uint32_t*)&sGh[(r0 + 8) * ST_S + kb + q2 + 8];
#pragma unroll
                for (int nt = 0; nt < 2; nt++) mma16816h(yd[mt][nt], aa, bb[nt]);
            }
        }
        for (int kb = 0; kb < 128; kb += 16) {
            uint32_t bb[2][2];
#pragma unroll
            for (int nt = 0; nt < 2; nt++) {
                int c0 = wn * 16 + nt * 8 + grp;
                bb[nt][0] = *(const uint32_t*)&sP[c0 * SB_S + kb + q2];
                bb[nt][1] = *(const uint32_t*)&sP[c0 * SB_S + kb + q2 + 8];
            }
#pragma unroll
            for (int mt = 0; mt < 2; mt++) {
                int r0 = wm * 32 + mt * 16 + grp;
                uint32_t aa[4];
                aa[0] = *(const uint32_t*)&sC[r0 * SB_S + kb + q2];
                aa[1] = *(const uint32_t*)&sC[(r0 + 8) * SB_S + kb + q2];
                aa[2] = *(const uint32_t*)&sC[r0 * SB_S + kb + q2 + 8];
                aa[3] = *(const uint32_t*)&sC[(r0 + 8) * SB_S + kb + q2 + 8];
#pragma unroll
                for (int nt = 0; nt < 2; nt++) mma16816h(yo[mt][nt], aa, bb[nt]);
            }
        }

        float Dh = Dvec[h];
        float eT[2][2];
#pragma unroll
        for (int mt = 0; mt < 2; mt++)
#pragma unroll
            for (int rr = 0; rr < 2; rr++)
                eT[mt][rr] = __expf(s_cs[wm * 32 + mt * 16 + grp + rr * 8]);
#pragma unroll
        for (int mt = 0; mt < 2; mt++)
#pragma unroll
            for (int nt = 0; nt < 2; nt++) {
                int t0 = wm * 32 + mt * 16 + grp;
                int p0 = wn * 16 + nt * 8 + q2;
#pragma unroll
                for (int rr = 0; rr < 2; rr++) {
                    int t = t0 + rr * 8;
                    float e = eT[mt][rr];
                    __half2 xv2 = *(const __half2*)&xrow[(size_t)t * CONVD + h * 64 + p0];
                    float2 xv = __half22float2(xv2);
                    float ox = fmaf(e, yo[mt][nt][rr * 2 + 0], fmaf(Dh, xv.x, yd[mt][nt][rr * 2 + 0]));
                    float oy = fmaf(e, yo[mt][nt][rr * 2 + 1], fmaf(Dh, xv.y, yd[mt][nt][rr * 2 + 1]));
                    *(__half2*)&y[(size_t)(row0 + t) * DSSM + h * 64 + p0] =
                        __floats2half2_rn(ox, oy);
                }
            }
    }
}

// ---------------- gate (y * silu(z)) + RMSNorm -> fp16 ----------------
__global__ void gate_norm_kernel(const __half* __restrict__ zxh,
                                 const __half* __restrict__ y,
                                 const float* __restrict__ norm_w,
                                 __half* __restrict__ ynh) {
    const int row = blockIdx.x;
    const int tid = threadIdx.x;
    const __half* yrow = y + (size_t)row * DSSM;
    const __half* zrow = zxh + (size_t)row * DIP;
    float v[8];
    float ss = 0.f;
#pragma unroll
    for (int k = 0; k < 8; k++) {
        int e = tid + k * 256;
        float z = __half2float(zrow[e]);
        float vv = __half2float(yrow[e]) * fast_silu(z);
        v[k] = vv;
        ss = fmaf(vv, vv, ss);
    }
    __shared__ float red[256];
    red[tid] = ss;
    __syncthreads();
    for (int s = 128; s > 0; s >>= 1) {
        if (tid < s) red[tid] += red[tid + s];
        __syncthreads();
    }
    float r = rsqrtf(red[0] / (float)DSSM + 1e-5f);
#pragma unroll
    for (int k = 0; k < 8; k++) {
        int e = tid + k * 256;
        ynh[(size_t)row * DSSM + e] = __float2half(v[k] * r * norm_w[e]);
    }
}

// ---------------- host launch ----------------
extern "C" void kernel_launch(void* const* d_in, const int* in_sizes, int n_in,
                              void* d_out, int out_size) {
    const float* u       = (const float*)d_in[0];
    const float* W_in    = (const float*)d_in[1];
    const float* conv_w  = (const float*)d_in[2];
    const float* conv_b  = (const float*)d_in[3];
    const float* dt_bias = (const float*)d_in[4];
    const float* A_log   = (const float*)d_in[5];
    const float* Dv      = (const float*)d_in[6];
    const float* norm_w  = (const float*)d_in[7];
    const float* W_out   = (const float*)d_in[8];
    float* out = (float*)d_out;

    void *p_zxh, *p_xbc, *p_y, *p_states, *p_prev, *p_cs, *p_dt, *p_scale;
    void *p_uh, *p_wih, *p_ynh, *p_woh;
    cudaGetSymbolAddress(&p_zxh, g_zxh);
    cudaGetSymbolAddress(&p_xbc, g_xbc);
    cudaGetSymbolAddress(&p_y, g_y);
    cudaGetSymbolAddress(&p_states, g_states);
    cudaGetSymbolAddress(&p_prev, g_prev);
    cudaGetSymbolAddress(&p_cs, g_cs);
    cudaGetSymbolAddress(&p_dt, g_dt);
    cudaGetSymbolAddress(&p_scale, g_scale);
    cudaGetSymbolAddress(&p_uh, g_uh);
    cudaGetSymbolAddress(&p_wih, g_wih);
    cudaGetSymbolAddress(&p_ynh, g_ynh);
    cudaGetSymbolAddress(&p_woh, g_woh);
    __half* zxh = (__half*)p_zxh;
    __half* xbc = (__half*)p_xbc;
    __half* y = (__half*)p_y;
    __half* states = (__half*)p_states;
    __half* prev = (__half*)p_prev;
    float* cs = (float*)p_cs;
    float* dtb = (float*)p_dt;
    float* scale = (float*)p_scale;
    __half* uh = (__half*)p_uh;
    __half* wih = (__half*)p_wih;
    __half* ynh = (__half*)p_ynh;
    __half* woh = (__half*)p_woh;

    cudaFuncSetAttribute(gemm_nt_fp16<__half>, cudaFuncAttributeMaxDynamicSharedMemorySize,
                         GEMM_SMEM);
    cudaFuncSetAttribute(gemm_nt_fp16<float>, cudaFuncAttributeMaxDynamicSharedMemorySize,
                         GEMM_SMEM);
    cudaFuncSetAttribute(ssm_states_kernel, cudaFuncAttributeMaxDynamicSharedMemorySize,
                         SM_K1A_BYTES);
    cudaFuncSetAttribute(ssm_y_kernel, cudaFuncAttributeMaxDynamicSharedMemorySize,
                         SM_K1B_BYTES);

    // 0. fp16 conversions (one launch)
    {
        int n1 = MROWS * D_MODEL / 4;
        int n2 = DIP * D_MODEL / 4;
        int n3 = D_MODEL * DSSM / 4;
        int total = n1 + n2 + n3;
        convert_all_kernel<<<(total + 255) / 256, 256>>>(u, uh, n1, W_in, wih, n2,
                                                         W_out, woh, n3);
    }

    // 1. in_proj (fp16, fp16 output)
    gemm_nt_fp16<__half><<<dim3((DIP + 127) / 128, MROWS / 128), 256, GEMM_SMEM>>>(
        uh, wih, zxh, MROWS, DIP, D_MODEL);

    // 2. conv1d + silu -> fp16
    {
        size_t total4 = (size_t)(MROWS / 4) * CONVD;
        conv_silu_kernel<<<(unsigned)((total4 + 255) / 256), 256>>>(zxh, conv_w, conv_b, xbc);
    }

    // 3a. states + dt/cs
    ssm_states_kernel<<<dim3(NC64, NH / HPB, BATCH), 256, SM_K1A_BYTES>>>(
        zxh, xbc, dt_bias, A_log, states, cs, dtb);

    // 3b. per-chunk scale precompute + inter-chunk recurrence
    scale_kernel<<<(BATCH * NC64 * NH + 255) / 256, 256>>>(cs, scale, BATCH * NC64 * NH);
    chunk_scan64<<<dim3(16, NH, BATCH), 256>>>(states, scale, prev);

    // 3c. fused Y (Y_diag + Y_off + D*x), fp16 write
    ssm_y_kernel<<<dim3(NC64, NH / HPB, BATCH), 256, SM_K1B_BYTES>>>(
        xbc, prev, cs, dtb, Dv, y);

    // 4. gate + RMSNorm -> fp16
    gate_norm_kernel<<<MROWS, 256>>>(zxh, y, norm_w, ynh);

    // 5. out_proj (fp16, fp32 output)
    gemm_nt_fp16<float><<<dim3(D_MODEL / 128, MROWS / 128), 256, GEMM_SMEM>>>(
        ynh, woh, out, MROWS, D_MODEL, DSSM);
}

// round 17
// speedup vs baseline: 1.1805x; 1.0871x over previous
#include <cuda_runtime.h>
#include <cuda_bf16.h>
#include <cuda_fp16.h>
#include <math.h>
#include <stdint.h>

#define BATCH 2
#define L_SEQ 4096
#define D_MODEL 1024
#define DIP 4384          // D_IN_PROJ
#define DSSM 2048
#define CONVD 2304        // CONV_DIM
#define NH 32
#define HD 64
#define DS 128
#define NC64 64           // chunks of 64 per batch
#define TCH 64
#define HPB 8             // heads per block
#define MROWS (BATCH * L_SEQ)   // 8192

// ---------------- scratch (device globals; no allocation) ----------------
__device__ __half g_zxh[(size_t)MROWS * DIP];
__device__ __half g_xbc[(size_t)MROWS * CONVD];
__device__ __half g_y[(size_t)MROWS * DSSM];
__device__ __half g_states[(size_t)BATCH * NC64 * NH * HD * DS];
__device__ __half g_prev[(size_t)BATCH * NC64 * NH * HD * DS];
__device__ float g_cs[(size_t)BATCH * NC64 * NH * TCH];
__device__ float g_dt[(size_t)BATCH * NC64 * NH * TCH];
__device__ float g_scale[(size_t)BATCH * NC64 * NH];

__device__ __half g_uh[(size_t)MROWS * D_MODEL];
__device__ __half g_wih[(size_t)DIP * D_MODEL];
__device__ __half g_ynh[(size_t)MROWS * DSSM];
__device__ __half g_woh[(size_t)D_MODEL * DSSM];

// ---------------- helpers ----------------
struct alignas(8) half4 { __half a, b, c, d; };

__device__ __forceinline__ float fast_silu(float x) {
    float t;
    asm("tanh.approx.f32 %0, %1;" : "=f"(t) : "f"(x * 0.5f));
    return 0.5f * x * (1.f + t);
}

__device__ __forceinline__ void mma16816h(float* d, const uint32_t* a, const uint32_t* b) {
    asm volatile(
        "mma.sync.aligned.m16n8k16.row.col.f32.f16.f16.f32 "
        "{%0,%1,%2,%3}, {%4,%5,%6,%7}, {%8,%9}, {%0,%1,%2,%3};"
        : "+f"(d[0]), "+f"(d[1]), "+f"(d[2]), "+f"(d[3])
        : "r"(a[0]), "r"(a[1]), "r"(a[2]), "r"(a[3]), "r"(b[0]), "r"(b[1]));
}

__device__ __forceinline__ void ldsm_x4(uint32_t& r0, uint32_t& r1, uint32_t& r2,
                                        uint32_t& r3, uint32_t addr) {
    asm volatile("ldmatrix.sync.aligned.m8n8.x4.shared.b16 {%0,%1,%2,%3}, [%4];"
                 : "=r"(r0), "=r"(r1), "=r"(r2), "=r"(r3) : "r"(addr));
}

__device__ __forceinline__ void cpasync16(uint32_t dst, const void* src, int szvalid) {
    asm volatile("cp.async.cg.shared.global [%0], [%1], 16, %2;"
                 :: "r"(dst), "l"(src), "r"(szvalid) : "memory");
}
#define CPASYNC_COMMIT() asm volatile("cp.async.commit_group;" ::: "memory")
#define CPASYNC_WAIT(n)  asm volatile("cp.async.wait_group %0;" :: "n"(n) : "memory")

// ---------------- merged fp32 -> fp16 convert (3 tensors, one launch) ----------------
__global__ void convert_all_kernel(const float* __restrict__ a, __half* __restrict__ ao, int n1,
                                   const float* __restrict__ b, __half* __restrict__ bo, int n2,
                                   const float* __restrict__ c, __half* __restrict__ co, int n3) {
    int i = blockIdx.x * 256 + threadIdx.x;
    const float* src;
    __half* dst;
    if (i < n1) { src = a; dst = ao; }
    else if (i < n1 + n2) { src = b; dst = bo; i -= n1; }
    else if (i < n1 + n2 + n3) { src = c; dst = co; i -= n1 + n2; }
    else return;
    float4 v = ((const float4*)src)[i];
    half4 hv = {__float2half(v.x), __float2half(v.y),
                __float2half(v.z), __float2half(v.w)};
    ((half4*)dst)[i] = hv;
}

// ---------------- chunk scale precompute ----------------
__global__ void scale_kernel(const float* __restrict__ cs, float* __restrict__ scale, int n) {
    int i = blockIdx.x * 256 + threadIdx.x;
    if (i < n) scale[i] = __expf(cs[(size_t)i * TCH + TCH - 1]);
}

// ---------------- fp16 single-pass GEMM (R14 pipeline: WAIT(2), 1 barrier/k) ----------------
#define GK 16
#define GPAD 24
#define NSTAGE 4
#define GEMM_SMEM (NSTAGE * 2 * 128 * GPAD * 2)   // 49152 bytes

template <typename OutT>
__global__ __launch_bounds__(256, 2) void gemm_nt_fp16(
    const __half* __restrict__ A, const __half* __restrict__ B,
    OutT* __restrict__ C, int M, int N, int K) {
    extern __shared__ __half smh[];
    __half* sA = smh;
    __half* sB = smh + NSTAGE * 128 * GPAD;

    const int tid = threadIdx.x;
    const int wid = tid >> 5, lane = tid & 31;
    const int wm = wid >> 2, wn = wid & 3;
    const int grp = lane >> 2, q2 = (lane & 3) * 2;
    const int rowBase = blockIdx.y * 128;
    const int colBase = blockIdx.x * 128;
    const int lrow = tid >> 1;
    const int lkh = (tid & 1) * 8;

    const int lmRow = lane & 15;
    const int lmK = (lane >> 4) << 3;

    const uint32_t sA_s = (uint32_t)__cvta_generic_to_shared(sA);
    const uint32_t sB_s = (uint32_t)__cvta_generic_to_shared(sB);

    float acc[4][4][4];
#pragma unroll
    for (int i = 0; i < 4; i++)
#pragma unroll
        for (int j = 0; j < 4; j++)
#pragma unroll
            for (int r = 0; r < 4; r++) acc[i][j][r] = 0.f;

    const int nk = K / GK;
#define SIDX(st, r, k) ((((st) * 128 + (r)) * GPAD) + (k))

    const __half* pA = A + (size_t)(rowBase + lrow) * K + lkh;
    int cn = colBase + lrow;
    int bok = (cn < N) ? 16 : 0;
    int cnc = (cn < N) ? cn : 0;
    const __half* pB = B + (size_t)cnc * K + lkh;

    auto load_stage = [&](int st, int kc) {
        int ko = kc * GK;
        cpasync16(sA_s + SIDX(st, lrow, lkh) * 2, pA + ko, 16);
        cpasync16(sB_s + SIDX(st, lrow, lkh) * 2, pB + ko, bok);
        CPASYNC_COMMIT();
    };

    load_stage(0, 0);
    if (nk > 1) load_stage(1, 1);

    for (int k = 0; k < nk; k++) {
        int st = k & (NSTAGE - 1);
        if (k + 2 < nk) {
            load_stage((k + 2) & (NSTAGE - 1), k + 2);
            CPASYNC_WAIT(2);
        } else if (k + 1 < nk) {
            CPASYNC_WAIT(1);
        } else {
            CPASYNC_WAIT(0);
        }
        __syncthreads();

        uint32_t bb[4][2];
        {
            uint32_t r0, r1, r2, r3;
            ldsm_x4(r0, r1, r2, r3, sB_s + SIDX(st, wn * 32 + lmRow, lmK) * 2);
            bb[0][0] = r0; bb[0][1] = r2; bb[1][0] = r1; bb[1][1] = r3;
            ldsm_x4(r0, r1, r2, r3, sB_s + SIDX(st, wn * 32 + 16 + lmRow, lmK) * 2);
            bb[2][0] = r0; bb[2][1] = r2; bb[3][0] = r1; bb[3][1] = r3;
        }
#pragma unroll
        for (int mt = 0; mt < 4; mt++) {
            int r0row = wm * 64 + mt * 16;
            uint32_t aa[4];
            ldsm_x4(aa[0], aa[1], aa[2], aa[3], sA_s + SIDX(st, r0row + lmRow, lmK) * 2);
#pragma unroll
            for (int nt = 0; nt < 4; nt++) mma16816h(acc[mt][nt], aa, bb[nt]);
        }
    }
#pragma unroll
    for (int mt = 0; mt < 4; mt++) {
#pragma unroll
        for (int nt = 0; nt < 4; nt++) {
            int colTile = colBase + wn * 32 + nt * 8;
            if (colTile >= N) continue;
            int r0 = rowBase + wm * 64 + mt * 16 + grp;
            int c0 = colTile + q2;
            if constexpr (sizeof(OutT) == 2) {
                *(__half2*)&C[(size_t)r0 * N + c0] =
                    __floats2half2_rn(acc[mt][nt][0], acc[mt][nt][1]);
                *(__half2*)&C[(size_t)(r0 + 8) * N + c0] =
                    __floats2half2_rn(acc[mt][nt][2], acc[mt][nt][3]);
            } else {
                *(float2*)&C[(size_t)r0 * N + c0] = make_float2(acc[mt][nt][0], acc[mt][nt][1]);
                *(float2*)&C[(size_t)(r0 + 8) * N + c0] = make_float2(acc[mt][nt][2], acc[mt][nt][3]);
            }
        }
    }
#undef SIDX
}

// ---------------- conv1d + SiLU : 4 t per thread, fp16 in/out ----------------
__global__ void conv_silu_kernel(const __half* __restrict__ zxh,
                                 const float* __restrict__ conv_w,
                                 const float* __restrict__ conv_b,
                                 __half* __restrict__ xbc) {
    size_t idx = (size_t)blockIdx.x * 256 + threadIdx.x;
    const size_t total = (size_t)(MROWS / 4) * CONVD;
    if (idx >= total) return;
    int cc = (int)(idx % CONVD);
    size_t r4 = idx / CONVD;
    size_t bt0 = r4 * 4;
    int t0 = (int)(bt0 % L_SEQ);

    float w0 = conv_w[cc * 4 + 0], w1 = conv_w[cc * 4 + 1];
    float w2 = conv_w[cc * 4 + 2], w3 = conv_w[cc * 4 + 3];
    float bia = conv_b[cc];

    float v[7];
#pragma unroll
    for (int j = 0; j < 7; j++) {
        int tt = t0 - 3 + j;
        v[j] = (tt >= 0) ? __half2float(zxh[(bt0 - 3 + j) * DIP + 2048 + cc]) : 0.f;
    }
#pragma unroll
    for (int i = 0; i < 4; i++) {
        float acc = bia;
        acc = fmaf(v[i + 0], w0, acc);
        acc = fmaf(v[i + 1], w1, acc);
        acc = fmaf(v[i + 2], w2, acc);
        acc = fmaf(v[i + 3], w3, acc);
        xbc[(bt0 + i) * CONVD + cc] = __float2half(fast_silu(acc));
    }
}

// ---------------- K1a: dt/cs + per-chunk states (double-buffered, 1 barrier/head) ----------------
#define SB_S 136
#define ST_S 66
#define SM_K1A_BYTES ((128 * ST_S + 2 * 64 * ST_S) * 2 + (2 * HPB * 64 + 2 * 64) * 4)

__global__ __launch_bounds__(256, 2) void ssm_states_kernel(
    const __half* __restrict__ zxh, const __half* __restrict__ xbc,
    const float* __restrict__ dt_bias, const float* __restrict__ A_log,
    __half* __restrict__ states, float* __restrict__ cs_out, float* __restrict__ dt_out) {
    extern __shared__ char smraw[];
    __half* sBT = (__half*)smraw;                  // 128 x ST_S
    __half* sXd = sBT + 128 * ST_S;                // 2 x 64 x ST_S (double buffer)
    float* s_dt = (float*)(sXd + 2 * 64 * ST_S);   // HPB x 64
    float* s_cs = s_dt + HPB * 64;                 // HPB x 64
    float* sEd = s_cs + HPB * 64;                  // 2 x 64 (combined dt*exp)

    const int c = blockIdx.x, hg = blockIdx.y, b = blockIdx.z;
    const int h0 = hg * HPB;
    const int tid = threadIdx.x;
    const int wid = tid >> 5, lane = tid & 31;
    const int wm = wid >> 2, wn = wid & 3;
    const int grp = lane >> 2, q2 = (lane & 3) * 2;
    const int row0 = b * L_SEQ + c * TCH;
    const __half* xrow = xbc + (size_t)row0 * CONVD;

    {
        int h = h0 + wid;
        float Ah = -__expf(A_log[h]);
        float bias = dt_bias[h];
        float d0 = __half2float(zxh[(size_t)(row0 + lane) * DIP + 4352 + h]) + bias;
        float d1 = __half2float(zxh[(size_t)(row0 + 32 + lane) * DIP + 4352 + h]) + bias;
        float dt0 = (d0 > 20.f) ? d0 : log1pf(__expf(d0));
        float dt1 = (d1 > 20.f) ? d1 : log1pf(__expf(d1));
        s_dt[wid * 64 + lane] = dt0;
        s_dt[wid * 64 + 32 + lane] = dt1;
        float v0 = dt0 * Ah, v1 = dt1 * Ah;
#pragma unroll
        for (int off = 1; off < 32; off <<= 1) {
            float n0 = __shfl_up_sync(0xffffffffu, v0, off);
            float n1 = __shfl_up_sync(0xffffffffu, v1, off);
            if (lane >= off) { v0 += n0; v1 += n1; }
        }
        v1 += __shfl_sync(0xffffffffu, v0, 31);
        s_cs[wid * 64 + lane] = v0;
        s_cs[wid * 64 + 32 + lane] = v1;
        size_t cbase = (((size_t)b * NC64 + c) * NH + h) * TCH;
        cs_out[cbase + lane] = v0;
        cs_out[cbase + 32 + lane] = v1;
        dt_out[cbase + lane] = dt0;
        dt_out[cbase + 32 + lane] = dt1;
    }

    for (int idx = tid; idx < 64 * 128; idx += 256) {
        int s = idx >> 7, n = idx & 127;
        sBT[n * ST_S + s] = xrow[(size_t)s * CONVD + 2048 + n];
    }
    __syncthreads();   // cs/dt + sBT ready

    // combined factor for a head: dt[s] * exp(csL - cs[s])
    auto calc_ed = [&](int buf, int hl) {
        if (tid < 64) {
            const float* csh = s_cs + hl * 64;
            sEd[buf * 64 + tid] = s_dt[hl * 64 + tid] * __expf(csh[63] - csh[tid]);
        }
    };
    // fill x~d for head hl into buffer buf (half2 loads, transposed stores)
    auto fill_xd = [&](int buf, int hl) {
        int h = h0 + hl;
        const float* ed = sEd + buf * 64;
        __half* dst = sXd + buf * 64 * ST_S;
        for (int idx = tid; idx < 64 * 32; idx += 256) {
            int s = idx >> 5, pr = (idx & 31) * 2;
            __half2 xv2 = *(const __half2*)&xrow[(size_t)s * CONVD + h * 64 + pr];
            float2 xf = __half22float2(xv2);
            float f = ed[s];
            dst[pr * ST_S + s] = __float2half(xf.x * f);
            dst[(pr + 1) * ST_S + s] = __float2half(xf.y * f);
        }
    };

    calc_ed(0, 0);
    __syncthreads();
    fill_xd(0, 0);
    calc_ed(1, 1);
    __syncthreads();   // buf0 + ed1 ready

    for (int hl = 0; hl < HPB; hl++) {
        int cur = hl & 1;
        int h = h0 + hl;
        if (hl + 1 < HPB) fill_xd(cur ^ 1, hl + 1);
        if (hl + 2 < HPB) calc_ed(cur, hl + 2);

        const __half* sXdc = sXd + cur * 64 * ST_S;
        float st[2][4][4];
#pragma unroll
        for (int i = 0; i < 2; i++)
#pragma unroll
            for (int j = 0; j < 4; j++)
#pragma unroll
                for (int r = 0; r < 4; r++) st[i][j][r] = 0.f;
        for (int kb = 0; kb < 64; kb += 16) {
            uint32_t bb[4][2];
#pragma unroll
            for (int nt = 0; nt < 4; nt++) {
                int c0 = wn * 32 + nt * 8 + grp;
                bb[nt][0] = *(const uint32_t*)&sBT[c0 * ST_S + kb + q2];
                bb[nt][1] = *(const uint32_t*)&sBT[c0 * ST_S + kb + q2 + 8];
            }
#pragma unroll
            for (int mt = 0; mt < 2; mt++) {
                int r0 = wm * 32 + mt * 16 + grp;
                uint32_t aa[4];
                aa[0] = *(const uint32_t*)&sXdc[r0 * ST_S + kb + q2];
                aa[1] = *(const uint32_t*)&sXdc[(r0 + 8) * ST_S + kb + q2];
                aa[2] = *(const uint32_t*)&sXdc[r0 * ST_S + kb + q2 + 8];
                aa[3] = *(const uint32_t*)&sXdc[(r0 + 8) * ST_S + kb + q2 + 8];
#pragma unroll
                for (int nt = 0; nt < 4; nt++) mma16816h(st[mt][nt], aa, bb[nt]);
            }
        }
        size_t sbase = (((size_t)b * NC64 + c) * NH + h) * (size_t)(HD * DS);
#pragma unroll
        for (int mt = 0; mt < 2; mt++)
#pragma unroll
            for (int nt = 0; nt < 4; nt++) {
                int p0 = wm * 32 + mt * 16 + grp;
                int n0 = wn * 32 + nt * 8 + q2;
                *(__half2*)&states[sbase + (size_t)p0 * DS + n0] =
                    __floats2half2_rn(st[mt][nt][0], st[mt][nt][1]);
                *(__half2*)&states[sbase + (size_t)(p0 + 8) * DS + n0] =
                    __floats2half2_rn(st[mt][nt][2], st[mt][nt][3]);
            }
        __syncthreads();   // next buffer filled + ed updated; safe to proceed
    }
}

// ---------------- K2: inter-chunk recurrence (precomputed scales) ----------------
__global__ void chunk_scan64(const __half* __restrict__ states,
                             const float* __restrict__ scale,
                             __half* __restrict__ prev) {
    const int seg = blockIdx.x, h = blockIdx.y, b = blockIdx.z;
    const int e2 = seg * 256 + threadIdx.x;
    float2 P = make_float2(0.f, 0.f);
    for (int c = 0; c < NC64; c++) {
        size_t base = ((size_t)b * NC64 + c) * NH + h;
        float sc = __ldg(&scale[base]);
        size_t off = base * (size_t)(HD * DS / 2) + e2;
        ((__half2*)prev)[off] = __floats2half2_rn(P.x, P.y);
        float2 sv = __half22float2(((const __half2*)states)[off]);
        P.x = fmaf(P.x, sc, sv.x);
        P.y = fmaf(P.y, sc, sv.y);
    }
}

// ---------------- K1b: fused Y, cp.async double-buffered prev ----------------
#define SM_K1B_BYTES ((4 * 64 * SB_S + 2 * 64 * ST_S) * 2 + (64 * ST_S + 2 * 64) * 4)

__global__ __launch_bounds__(256, 2) void ssm_y_kernel(
    const __half* __restrict__ xbc, const __half* __restrict__ prev,
    const float* __restrict__ cs, const float* __restrict__ dt,
    const float* __restrict__ Dvec, __half* __restrict__ y) {
    extern __shared__ char smraw[];
    __half* sB = (__half*)smraw;                 // 64 x SB_S
    __half* sC = sB + 64 * SB_S;                 // 64 x SB_S
    __half* sP = sC + 64 * SB_S;                 // 2 x 64 x SB_S (double buffer)
    __half* sGh = sP + 2 * 64 * SB_S;            // 64 x ST_S
    __half* sX = sGh + 64 * ST_S;                // 64 x ST_S
    float* sG = (float*)(sX + 64 * ST_S);        // 64 x ST_S
    float* s_cs = sG + 64 * ST_S;                // 64
    float* s_dt = s_cs + 64;                     // 64

    const int c = blockIdx.x, hg = blockIdx.y, b = blockIdx.z;
    const int h0 = hg * HPB;
    const int tid = threadIdx.x;
    const int wid = tid >> 5, lane = tid & 31;
    const int wm = wid >> 2, wn = wid & 3;
    const int grp = lane >> 2, q2 = (lane & 3) * 2;
    const int row0 = b * L_SEQ + c * TCH;
    const __half* xrow = xbc + (size_t)row0 * CONVD;
    const uint32_t sP_s = (uint32_t)__cvta_generic_to_shared(sP);

    // prefetch prev for head h into sP buffer buf (4 x 16B per thread)
    auto prefetch_prev = [&](int buf, int h) {
        size_t pbase = (((size_t)b * NC64 + c) * NH + h) * (size_t)(HD * DS);
        const char* src = (const char*)(prev + pbase);
#pragma unroll
        for (int j = 0; j < 4; j++) {
            int ci = tid * 4 + j;
            int p = ci >> 4, cc2 = ci & 15;
            cpasync16(sP_s + (uint32_t)(buf * 64 * SB_S + p * SB_S) * 2 + cc2 * 16,
                      src + p * DS * 2 + cc2 * 16, 16);
        }
        CPASYNC_COMMIT();
    };

    for (int idx = tid; idx < 64 * 128; idx += 256) {
        int s = idx >> 7, n = idx & 127;
        sB[s * SB_S + n] = xrow[(size_t)s * CONVD + 2048 + n];
        sC[s * SB_S + n] = xrow[(size_t)s * CONVD + 2176 + n];
    }
    prefetch_prev(0, h0);
    __syncthreads();

    // G = C * B^T (head-independent)
    {
        float g[2][2][4];
#pragma unroll
        for (int i = 0; i < 2; i++)
#pragma unroll
            for (int j = 0; j < 2; j++)
#pragma unroll
                for (int r = 0; r < 4; r++) g[i][j][r] = 0.f;
        for (int kb = 0; kb < 128; kb += 16) {
            uint32_t bb[2][2];
#pragma unroll
            for (int nt = 0; nt < 2; nt++) {
                int c0 = wn * 16 + nt * 8 + grp;
                bb[nt][0] = *(const uint32_t*)&sB[c0 * SB_S + kb + q2];
                bb[nt][1] = *(const uint32_t*)&sB[c0 * SB_S + kb + q2 + 8];
            }
#pragma unroll
            for (int mt = 0; mt < 2; mt++) {
                int r0 = wm * 32 + mt * 16 + grp;
                uint32_t aa[4];
                aa[0] = *(const uint32_t*)&sC[r0 * SB_S + kb + q2];
                aa[1] = *(const uint32_t*)&sC[(r0 + 8) * SB_S + kb + q2];
                aa[2] = *(const uint32_t*)&sC[r0 * SB_S + kb + q2 + 8];
                aa[3] = *(const uint32_t*)&sC[(r0 + 8) * SB_S + kb + q2 + 8];
#pragma unroll
                for (int nt = 0; nt < 2; nt++) mma16816h(g[mt][nt], aa, bb[nt]);
            }
        }
#pragma unroll
        for (int mt = 0; mt < 2; mt++)
#pragma unroll
            for (int nt = 0; nt < 2; nt++) {
                int t = wm * 32 + mt * 16 + grp;
                int s = wn * 16 + nt * 8 + q2;
                *(float2*)&sG[t * ST_S + s] = make_float2(g[mt][nt][0], g[mt][nt][1]);
                *(float2*)&sG[(t + 8) * ST_S + s] = make_float2(g[mt][nt][2], g[mt][nt][3]);
            }
    }

    __syncthreads();
    for (int idx = tid; idx < 64 * 64; idx += 256) {
        int t = idx >> 6, s = idx & 63;
        if (t < s) sGh[t * ST_S + s] = __ushort_as_half(0);
    }

    for (int hl = 0; hl < HPB; hl++) {
        int h = h0 + hl;
        int cur = hl & 1;
        CPASYNC_WAIT(0);           // sP[cur] transfer complete
        size_t cbase = (((size_t)b * NC64 + c) * NH + h) * TCH;
        if (tid < 64) {
            s_cs[tid] = cs[cbase + tid];
            s_dt[tid] = dt[cbase + tid];
        }
        __syncthreads();           // sP[cur] visible; prev head's mma reads ordered
        if (hl + 1 < HPB) prefetch_prev(cur ^ 1, h0 + hl + 1);

        for (int idx = tid; idx < 64 * 64; idx += 256) {
            int t = idx >> 6, s = idx & 63;
            if (t >= s) {
                sGh[t * ST_S + s] =
                    __float2half(sG[t * ST_S + s] * __expf(s_cs[t] - s_cs[s]));
            }
            int p = idx & 63, ss = idx >> 6;
            float xv = __half2float(xrow[(size_t)ss * CONVD + h * 64 + p]);
            sX[p * ST_S + ss] = __float2half(xv * s_dt[ss]);
        }
        __syncthreads();

        const __half* sPc = sP + cur * 64 * SB_S;
        float yd[2][2][4], yo[2][2][4];
#pragma unroll
        for (int i = 0; i < 2; i++)
#pragma unroll
            for (int j = 0; j < 2; j++)
#pragma unroll
                for (int r = 0; r < 4; r++) { yd[i][j][r] = 0.f; yo[i][j][r] = 0.f; }
        for (int kb = 0; kb < 64; kb += 16) {
            uint32_t bb[2][2];
#pragma unroll
            for (int nt = 0; nt < 2; nt++) {
                int c0 = wn * 16 + nt * 8 + grp;
                bb[nt][0] = *(const uint32_t*)&sX[c0 * ST_S + kb + q2];
                bb[nt][1] = *(const uint32_t*)&sX[c0 * ST_S + kb + q2 + 8];
            }
#pragma unroll
            for (int mt = 0; mt < 2; mt++) {
                int r0 = wm * 32 + mt * 16 + grp;
                uint32_t aa[4];
                aa[0] = *(const uint32_t*)&sGh[r0 * ST_S + kb + q2];
                aa[1] = *(const uint32_t*)&sGh[(r0 + 8) * ST_S + kb + q2];
                aa[2] = *(const uint32_t*)&sGh[r0 * ST_S + kb + q2 + 8];
                aa[3] = *(const uint32_t*)&sGh[(r0 + 8) * ST_S + kb + q2 + 8];
#pragma unroll
                for (int nt = 0; nt < 2; nt++) mma16816h(yd[mt][nt], aa, bb[nt]);
            }
        }
        for (int kb = 0; kb < 128; kb += 16) {
            uint32_t bb[2][2];
#pragma unroll
            for (int nt = 0; nt < 2; nt++) {
                int c0 = wn * 16 + nt * 8 + grp;
                bb[nt][0] = *(const uint32_t*)&sPc[c0 * SB_S + kb + q2];
                bb[nt][1] = *(const uint32_t*)&sPc[c0 * SB_S + kb + q2 + 8];
            }
#pragma unroll
            for (int mt = 0; mt < 2; mt++) {
                int r0 = wm * 32 + mt * 16 + grp;
                uint32_t aa[4];
                aa[0] = *(const uint32_t*)&sC[r0 * SB_S + kb + q2];
                aa[1] = *(const uint32_t*)&sC[(r0 + 8) * SB_S + kb + q2];
                aa[2] = *(const uint32_t*)&sC[r0 * SB_S + kb + q2 + 8];
                aa[3] = *(const uint32_t*)&sC[(r0 + 8) * SB_S + kb + q2 + 8];
#pragma unroll
                for (int nt = 0; nt < 2; nt++) mma16816h(yo[mt][nt], aa, bb[nt]);
            }
        }

        float Dh = Dvec[h];
        float eT[2][2];
#pragma unroll
        for (int mt = 0; mt < 2; mt++)
#pragma unroll
            for (int rr = 0; rr < 2; rr++)
                eT[mt][rr] = __expf(s_cs[wm * 32 + mt * 16 + grp + rr * 8]);
#pragma unroll
        for (int mt = 0; mt < 2; mt++)
#pragma unroll
            for (int nt = 0; nt < 2; nt++) {
                int t0 = wm * 32 + mt * 16 + grp;
                int p0 = wn * 16 + nt * 8 + q2;
#pragma unroll
                for (int rr = 0; rr < 2; rr++) {
                    int t = t0 + rr * 8;
                    float e = eT[mt][rr];
                    __half2 xv2 = *(const __half2*)&xrow[(size_t)t * CONVD + h * 64 + p0];
                    float2 xv = __half22float2(xv2);
                    float ox = fmaf(e, yo[mt][nt][rr * 2 + 0], fmaf(Dh, xv.x, yd[mt][nt][rr * 2 + 0]));
                    float oy = fmaf(e, yo[mt][nt][rr * 2 + 1], fmaf(Dh, xv.y, yd[mt][nt][rr * 2 + 1]));
                    *(__half2*)&y[(size_t)(row0 + t) * DSSM + h * 64 + p0] =
                        __floats2half2_rn(ox, oy);
                }
            }
    }
}

// ---------------- gate (y * silu(z)) + RMSNorm -> fp16 ----------------
__global__ void gate_norm_kernel(const __half* __restrict__ zxh,
                                 const __half* __restrict__ y,
                                 const float* __restrict__ norm_w,
                                 __half* __restrict__ ynh) {
    const int row = blockIdx.x;
    const int tid = threadIdx.x;
    const __half* yrow = y + (size_t)row * DSSM;
    const __half* zrow = zxh + (size_t)row * DIP;
    float v[8];
    float ss = 0.f;
#pragma unroll
    for (int k = 0; k < 8; k++) {
        int e = tid + k * 256;
        float z = __half2float(zrow[e]);
        float vv = __half2float(yrow[e]) * fast_silu(z);
        v[k] = vv;
        ss = fmaf(vv, vv, ss);
    }
    __shared__ float red[256];
    red[tid] = ss;
    __syncthreads();
    for (int s = 128; s > 0; s >>= 1) {
        if (tid < s) red[tid] += red[tid + s];
        __syncthreads();
    }
    float r = rsqrtf(red[0] / (float)DSSM + 1e-5f);
#pragma unroll
    for (int k = 0; k < 8; k++) {
        int e = tid + k * 256;
        ynh[(size_t)row * DSSM + e] = __float2half(v[k] * r * norm_w[e]);
    }
}

// ---------------- host launch ----------------
extern "C" void kernel_launch(void* const* d_in, const int* in_sizes, int n_in,
                              void* d_out, int out_size) {
    const float* u       = (const float*)d_in[0];
    const float* W_in    = (const float*)d_in[1];
    const float* conv_w  = (const float*)d_in[2];
    const float* conv_b  = (const float*)d_in[3];
    const float* dt_bias = (const float*)d_in[4];
    const float* A_log   = (const float*)d_in[5];
    const float* Dv      = (const float*)d_in[6];
    const float* norm_w  = (const float*)d_in[7];
    const float* W_out   = (const float*)d_in[8];
    float* out = (float*)d_out;

    void *p_zxh, *p_xbc, *p_y, *p_states, *p_prev, *p_cs, *p_dt, *p_scale;
    void *p_uh, *p_wih, *p_ynh, *p_woh;
    cudaGetSymbolAddress(&p_zxh, g_zxh);
    cudaGetSymbolAddress(&p_xbc, g_xbc);
    cudaGetSymbolAddress(&p_y, g_y);
    cudaGetSymbolAddress(&p_states, g_states);
    cudaGetSymbolAddress(&p_prev, g_prev);
    cudaGetSymbolAddress(&p_cs, g_cs);
    cudaGetSymbolAddress(&p_dt, g_dt);
    cudaGetSymbolAddress(&p_scale, g_scale);
    cudaGetSymbolAddress(&p_uh, g_uh);
    cudaGetSymbolAddress(&p_wih, g_wih);
    cudaGetSymbolAddress(&p_ynh, g_ynh);
    cudaGetSymbolAddress(&p_woh, g_woh);
    __half* zxh = (__half*)p_zxh;
    __half* xbc = (__half*)p_xbc;
    __half* y = (__half*)p_y;
    __half* states = (__half*)p_states;
    __half* prev = (__half*)p_prev;
    float* cs = (float*)p_cs;
    float* dtb = (float*)p_dt;
    float* scale = (float*)p_scale;
    __half* uh = (__half*)p_uh;
    __half* wih = (__half*)p_wih;
    __half* ynh = (__half*)p_ynh;
    __half* woh = (__half*)p_woh;

    cudaFuncSetAttribute(gemm_nt_fp16<__half>, cudaFuncAttributeMaxDynamicSharedMemorySize,
                         GEMM_SMEM);
    cudaFuncSetAttribute(gemm_nt_fp16<float>, cudaFuncAttributeMaxDynamicSharedMemorySize,
                         GEMM_SMEM);
    cudaFuncSetAttribute(ssm_states_kernel, cudaFuncAttributeMaxDynamicSharedMemorySize,
                         SM_K1A_BYTES);
    cudaFuncSetAttribute(ssm_y_kernel, cudaFuncAttributeMaxDynamicSharedMemorySize,
                         SM_K1B_BYTES);

    // 0. fp16 conversions (one launch)
    {
        int n1 = MROWS * D_MODEL / 4;
        int n2 = DIP * D_MODEL / 4;
        int n3 = D_MODEL * DSSM / 4;
        int total = n1 + n2 + n3;
        convert_all_kernel<<<(total + 255) / 256, 256>>>(u, uh, n1, W_in, wih, n2,
                                                         W_out, woh, n3);
    }

    // 1. in_proj (fp16, fp16 output)
    gemm_nt_fp16<__half><<<dim3((DIP + 127) / 128, MROWS / 128), 256, GEMM_SMEM>>>(
        uh, wih, zxh, MROWS, DIP, D_MODEL);

    // 2. conv1d + silu -> fp16
    {
        size_t total4 = (size_t)(MROWS / 4) * CONVD;
        conv_silu_kernel<<<(unsigned)((total4 + 255) / 256), 256>>>(zxh, conv_w, conv_b, xbc);
    }

    // 3a. states + dt/cs (pipelined)
    ssm_states_kernel<<<dim3(NC64, NH / HPB, BATCH), 256, SM_K1A_BYTES>>>(
        zxh, xbc, dt_bias, A_log, states, cs, dtb);

    // 3b. per-chunk scale precompute + inter-chunk recurrence
    scale_kernel<<<(BATCH * NC64 * NH + 255) / 256, 256>>>(cs, scale, BATCH * NC64 * NH);
    chunk_scan64<<<dim3(16, NH, BATCH), 256>>>(states, scale, prev);

    // 3c. fused Y (Y_diag + Y_off + D*x), prev prefetched via cp.async
    ssm_y_kernel<<<dim3(NC64, NH / HPB, BATCH), 256, SM_K1B_BYTES>>>(
        xbc, prev, cs, dtb, Dv, y);

    // 4. gate + RMSNorm -> fp16
    gate_norm_kernel<<<MROWS, 256>>>(zxh, y, norm_w, ynh);

    // 5. out_proj (fp16, fp32 output)
    gemm_nt_fp16<float><<<dim3(D_MODEL / 128, MROWS / 128), 256, GEMM_SMEM>>>(
        ynh, woh, out, MROWS, D_MODEL, DSSM);
}